// round 16
// baseline (speedup 1.0000x reference)
#include <cuda_runtime.h>
#include <math.h>

#define N_TOK   8192
#define IN_F    768
#define OUT_F   256
#define C1f     0.6f
#define C2f     0.4f
#define NBLK    148
#define NWORK   128           // worker blocks: 2048 warps x 4 rows = 8192
#define NPROD   20            // producer blocks for w = W@a (blocks 128..147)
#define NFIN    32            // finisher blocks: 8 output cols each
#define NTHR    512
#define NWPB    16            // warps per block
#define MAXC    32            // slow-path candidate cap
#define THRESH  0.0535f       // 87.4 / (0.2 * 8192): beyond this, exp == 0 exactly

// ---- scratch (static device memory) ----
__device__ float    g_w[2 * IN_F];
__device__ float    g_s1[N_TOK];
__device__ float    g_s2[N_TOK];
__device__ int      g_scnt[NWORK];
__device__ int      g_srow[NWORK][4];
__device__ float    g_sval[NWORK][4];
__device__ float    g_y[IN_F];          // slow path only
__device__ unsigned g_done0 = 0u, g_cnt2 = 0u, g_done3 = 0u, g_done4 = 0u;

__device__ __forceinline__ float warp_sum(float v) {
    #pragma unroll
    for (int o = 16; o > 0; o >>= 1) v += __shfl_xor_sync(0xffffffffu, v, o);
    return v;
}
__device__ __forceinline__ float warp_max(float v) {
    #pragma unroll
    for (int o = 16; o > 0; o >>= 1) v = fmaxf(v, __shfl_xor_sync(0xffffffffu, v, o));
    return v;
}

__global__ void __launch_bounds__(NTHR, 1)
fused_gat(const float* __restrict__ X, const float* __restrict__ W,
          const float* __restrict__ a, float* __restrict__ out) {
    const int t = threadIdx.x, bid = blockIdx.x;
    const int warp = t >> 5, lane = t & 31;

    __shared__ float sw[2 * IN_F];      // worker: w1/w2 ; finisher: y staging (768)
    __shared__ float sbuf[NTHR];
    __shared__ float bmax_sh, gmax_sh;
    __shared__ int   lc_cnt, ovf_sh, ccnt_sh;
    __shared__ int   crows[MAXC];
    __shared__ float cvals[MAXC];
    __shared__ float rsv[MAXC];

    // ================= PRODUCERS: blocks 128..147 compute w = W @ a ========
    if (bid >= NWORK) {
        int pb = bid - NWORK;                            // 0..19
        int base = (pb * 768) / NPROD;
        int end  = ((pb + 1) * 768) / NPROD;             // 38-39 rows each
        for (int row = base + warp; row < end; row += NWPB) {
            float d1 = 0.f, d2 = 0.f;
            #pragma unroll
            for (int q = 0; q < 8; q++) {
                int c = q * 32 + lane;
                float w = W[row * OUT_F + c];
                d1 = fmaf(w, a[c], d1);
                d2 = fmaf(w, a[OUT_F + c], d2);
            }
            d1 = warp_sum(d1); d2 = warp_sum(d2);
            if (lane == 0) { g_w[row] = d1; g_w[IN_F + row] = d2; }
        }
        __syncthreads();
        if (t == 0) { __threadfence(); atomicAdd(&g_done0, 1u); }
        return;
    }

    // ================= WORKERS: blocks 0..127, 4 X-rows per warp ===========
    const int gw = bid * NWPB + warp;                    // 0 .. 2047
    float4 v0[6], v1[6], v2[6], v3[6];
    {
        const float4* p0 = (const float4*)(X + (size_t)(gw)        * IN_F);
        const float4* p1 = (const float4*)(X + (size_t)(gw + 2048) * IN_F);
        const float4* p2 = (const float4*)(X + (size_t)(gw + 4096) * IN_F);
        const float4* p3 = (const float4*)(X + (size_t)(gw + 6144) * IN_F);
        #pragma unroll
        for (int q = 0; q < 6; q++) v0[q] = p0[q * 32 + lane];
        #pragma unroll
        for (int q = 0; q < 6; q++) v1[q] = p1[q * 32 + lane];
        #pragma unroll
        for (int q = 0; q < 6; q++) v2[q] = p2[q * 32 + lane];
        #pragma unroll
        for (int q = 0; q < 6; q++) v3[q] = p3[q * 32 + lane];
    }

    // ---- gate 1: tight spin for the 20 w-producer blocks ----
    if (t == 0) {
        lc_cnt = 0;
        while (*((volatile unsigned*)&g_done0) < NPROD) { }
        __threadfence();
    }
    __syncthreads();
    // stage w into smem (1536 floats, 512 threads: 3 each)
    sw[t] = __ldcg(&g_w[t]);
    sw[t + NTHR] = __ldcg(&g_w[t + NTHR]);
    sw[t + 2 * NTHR] = __ldcg(&g_w[t + 2 * NTHR]);
    __syncthreads();

    {
        float d1r[4] = {0.f, 0.f, 0.f, 0.f};
        float d2r[4] = {0.f, 0.f, 0.f, 0.f};
        #pragma unroll
        for (int q = 0; q < 6; q++) {
            int c = (q * 32 + lane) * 4;
            float w10 = sw[c],        w11 = sw[c+1],      w12 = sw[c+2],      w13 = sw[c+3];
            float w20 = sw[IN_F+c],   w21 = sw[IN_F+c+1], w22 = sw[IN_F+c+2], w23 = sw[IN_F+c+3];
            float4 A = v0[q], B = v1[q], C = v2[q], D = v3[q];
            d1r[0] = fmaf(A.x, w10, d1r[0]); d1r[0] = fmaf(A.y, w11, d1r[0]);
            d1r[0] = fmaf(A.z, w12, d1r[0]); d1r[0] = fmaf(A.w, w13, d1r[0]);
            d2r[0] = fmaf(A.x, w20, d2r[0]); d2r[0] = fmaf(A.y, w21, d2r[0]);
            d2r[0] = fmaf(A.z, w22, d2r[0]); d2r[0] = fmaf(A.w, w23, d2r[0]);
            d1r[1] = fmaf(B.x, w10, d1r[1]); d1r[1] = fmaf(B.y, w11, d1r[1]);
            d1r[1] = fmaf(B.z, w12, d1r[1]); d1r[1] = fmaf(B.w, w13, d1r[1]);
            d2r[1] = fmaf(B.x, w20, d2r[1]); d2r[1] = fmaf(B.y, w21, d2r[1]);
            d2r[1] = fmaf(B.z, w22, d2r[1]); d2r[1] = fmaf(B.w, w23, d2r[1]);
            d1r[2] = fmaf(C.x, w10, d1r[2]); d1r[2] = fmaf(C.y, w11, d1r[2]);
            d1r[2] = fmaf(C.z, w12, d1r[2]); d1r[2] = fmaf(C.w, w13, d1r[2]);
            d2r[2] = fmaf(C.x, w20, d2r[2]); d2r[2] = fmaf(C.y, w21, d2r[2]);
            d2r[2] = fmaf(C.z, w22, d2r[2]); d2r[2] = fmaf(C.w, w23, d2r[2]);
            d1r[3] = fmaf(D.x, w10, d1r[3]); d1r[3] = fmaf(D.y, w11, d1r[3]);
            d1r[3] = fmaf(D.z, w12, d1r[3]); d1r[3] = fmaf(D.w, w13, d1r[3]);
            d2r[3] = fmaf(D.x, w20, d2r[3]); d2r[3] = fmaf(D.y, w21, d2r[3]);
            d2r[3] = fmaf(D.z, w22, d2r[3]); d2r[3] = fmaf(D.w, w23, d2r[3]);
        }
        float s1mx = -INFINITY;
        #pragma unroll
        for (int k = 0; k < 4; k++) {
            d1r[k] = warp_sum(d1r[k]);
            d2r[k] = warp_sum(d2r[k]);
            s1mx = fmaxf(s1mx, d1r[k]);
        }
        if (lane == 0) {
            #pragma unroll
            for (int k = 0; k < 4; k++) {
                g_s1[gw + 2048 * k] = d1r[k];
                g_s2[gw + 2048 * k] = d2r[k];
            }
            sbuf[warp] = s1mx;
        }
        __syncthreads();
        if (warp == 0) {
            float m = (lane < NWPB) ? sbuf[lane] : -INFINITY;
            m = warp_max(m);
            if (lane == 0) bmax_sh = m;
        }
        __syncthreads();
        if (lane == 0) {
            float thr = bmax_sh - THRESH;
            #pragma unroll
            for (int k = 0; k < 4; k++) {
                if (d1r[k] >= thr) {
                    int p = atomicAdd(&lc_cnt, 1);
                    if (p < 4) { crows[p] = gw + 2048 * k; cvals[p] = d1r[k]; }
                }
            }
        }
        __syncthreads();
        if (t == 0) {
            int c = lc_cnt;
            g_scnt[bid] = c;
            #pragma unroll
            for (int k = 0; k < 4; k++)
                if (k < c) { g_srow[bid][k] = crows[k]; g_sval[bid][k] = cvals[k]; }
            __threadfence();
            atomicAdd(&g_cnt2, 1u);
        }
    }
    if (bid >= NFIN) return;              // only 32 finisher blocks continue

    // ---- prefetch W column-slice: cols [bid*8, bid*8+8), 12 k's per thread ----
    // t -> tcol = t&7 (column within slice), kg = t>>3 (0..63), k = kg*12 + j
    const int colbase = bid * 8;
    const int tcol = t & 7, kg = t >> 3;
    const int mycol = colbase + tcol;
    float wreg[12];
    #pragma unroll
    for (int j = 0; j < 12; j++)
        wreg[j] = W[(kg * 12 + j) * OUT_F + mycol];

    // ---- gate 2: tight spin for all 128 worker arrivals ----
    if (t == 0) {
        ovf_sh = 0; ccnt_sh = 0;
        while (*((volatile unsigned*)&g_cnt2) < (unsigned)NWORK) { }
        __threadfence();
    }
    __syncthreads();

    // ---- shortlist merge: single pass, filter from registers ----
    {
        float lm = -INFINITY;
        int myc = 0, rrow[4]; float rval[4];
        if (t < NWORK) {
            myc = __ldcg(&g_scnt[t]);
            if (myc > 4) ovf_sh = 1;                     // benign race
            #pragma unroll
            for (int k = 0; k < 4; k++) {
                if (k < myc) {
                    rrow[k] = __ldcg(&g_srow[t][k]);
                    rval[k] = __ldcg(&g_sval[t][k]);
                    lm = fmaxf(lm, rval[k]);
                }
            }
        }
        float wm = warp_max(lm);
        if (lane == 0) sbuf[warp] = wm;
        __syncthreads();
        if (warp == 0) {
            float m = (lane < NWPB) ? sbuf[lane] : -INFINITY;
            m = warp_max(m);
            if (lane == 0) gmax_sh = m;
        }
        __syncthreads();
        if (t < NWORK) {
            float thr = gmax_sh - THRESH;
            #pragma unroll
            for (int k = 0; k < 4; k++) {
                if (k < myc && rval[k] >= thr) {
                    int p = atomicAdd(&ccnt_sh, 1);
                    if (p < MAXC) { crows[p] = rrow[k]; cvals[p] = rval[k]; }
                }
            }
        }
        __syncthreads();
    }

    const float* ysrc;
    if (ovf_sh == 0 && ccnt_sh == 1) {
        // ---- FAST PATH: one candidate -> att one-hot -> y = X[row] exactly ----
        ysrc = X + (size_t)crows[0] * IN_F;
    } else {
        // ---- SLOW PATH (rare): block 0 computes exact softmax + y ----
        if (bid == 0) {
            float lmax = -INFINITY;
            for (int i = t; i < N_TOK; i += NTHR)
                lmax = fmaxf(lmax, __ldcg(&g_s1[i]));
            float wm = warp_max(lmax);
            if (lane == 0) sbuf[warp] = wm;
            __syncthreads();
            if (warp == 0) {
                float m = (lane < NWPB) ? sbuf[lane] : -INFINITY;
                m = warp_max(m);
                if (lane == 0) { gmax_sh = m; ccnt_sh = 0; }
            }
            __syncthreads();
            float thr = gmax_sh - THRESH;
            for (int i = t; i < N_TOK; i += NTHR) {
                if (__ldcg(&g_s1[i]) >= thr) {
                    int p = atomicAdd(&ccnt_sh, 1);
                    if (p < MAXC) crows[p] = i;
                }
            }
            __syncthreads();
            int cc = min(ccnt_sh, MAXC);
            for (int s = 0; s < cc; s++) {
                float s1c = __ldcg(&g_s1[crows[s]]);
                float acc = 0.f;
                for (int j = t; j < N_TOK; j += NTHR)
                    acc += fabsf(s1c + __ldcg(&g_s2[j]));
                acc = warp_sum(acc);
                if (lane == 0) sbuf[warp] = acc;
                __syncthreads();
                if (warp == 0) {
                    float v = (lane < NWPB) ? sbuf[lane] : 0.f;
                    v = warp_sum(v);
                    if (lane == 0) rsv[s] = fmaf(C1f * 8192.f, s1c, C2f * v);
                }
                __syncthreads();
            }
            float m = -INFINITY;
            for (int s = 0; s < cc; s++) m = fmaxf(m, rsv[s]);
            float S = 0.f;
            for (int s = 0; s < cc; s++) S += expf(rsv[s] - m);
            float invS = 1.f / S;
            for (int i = t; i < IN_F; i += NTHR) {
                float y = 0.f;
                for (int s = 0; s < cc; s++) {
                    float e = expf(rsv[s] - m);
                    if (e != 0.f)
                        y = fmaf(e * invS, __ldcg(&X[(size_t)crows[s] * IN_F + i]), y);
                }
                g_y[i] = y;
            }
            __threadfence();
            __syncthreads();
            if (t == 0) atomicExch(&g_done3, 1u);
        }
        if (t == 0) {
            while (*((volatile unsigned*)&g_done3) == 0u) { }
            __threadfence();
        }
        __syncthreads();
        ysrc = g_y;
    }

    // ---- P4: column-partitioned GEMV: this block fully owns 8 output cols ----
    {
        // stage y (768 floats) into smem (reuse sw)
        sw[t] = __ldcg(&ysrc[t]);
        if (t < IN_F - NTHR) sw[NTHR + t] = __ldcg(&ysrc[NTHR + t]);
        __syncthreads();
        float partial = 0.f;
        #pragma unroll
        for (int j = 0; j < 12; j++)
            partial = fmaf(sw[kg * 12 + j], wreg[j], partial);
        sbuf[t] = partial;
        __syncthreads();
        // tree-reduce over kg (64 groups), col-aligned strides (multiples of 8)
        #pragma unroll
        for (int s = 256; s >= 8; s >>= 1) {
            if (t < s) sbuf[t] += sbuf[t + s];
            __syncthreads();
        }
        if (t < 8) {
            float o = sbuf[t];
            out[colbase + t] = (o > 0.f) ? o : expm1f(o);
        }
        // off-critical-path cleanup: last finisher resets flags for next replay
        __syncthreads();
        if (t == 0) {
            if (atomicAdd(&g_done4, 1u) == NFIN - 1) {
                g_done0 = 0u; g_cnt2 = 0u; g_done3 = 0u; g_done4 = 0u;
            }
        }
    }
}

extern "C" void kernel_launch(void* const* d_in, const int* in_sizes, int n_in,
                              void* d_out, int out_size) {
    const float* X = (const float*)d_in[0];   // [8192, 768]
    const float* W = (const float*)d_in[1];   // [768, 256]
    const float* a = (const float*)d_in[2];   // [512, 1]
    float* out = (float*)d_out;               // [256]

    fused_gat<<<NBLK, NTHR>>>(X, W, a, out);
}

// round 17
// speedup vs baseline: 1.1577x; 1.1577x over previous
#include <cuda_runtime.h>
#include <math.h>

#define N_TOK   8192
#define IN_F    768
#define OUT_F   256
#define C1f     0.6f
#define C2f     0.4f
#define NBLK    148
#define NWORK   128           // worker blocks: 2048 warps x 4 rows = 8192
#define NPROD   20            // producer blocks for w = W@a (blocks 128..147)
#define NTHR    512           // 512 thr/block -> 128-reg budget, real front-batching
#define NWPB    16            // warps per block
#define MAXC    32            // slow-path candidate cap
#define THRESH  0.0535f       // 87.4 / (0.2 * 8192): beyond this, exp == 0 exactly

// ---- scratch (static device memory) ----
__device__ float    g_w[2 * IN_F];
__device__ float    g_s1[N_TOK];
__device__ float    g_s2[N_TOK];
__device__ int      g_scnt[NWORK];
__device__ int      g_srow[NWORK][4];
__device__ float    g_sval[NWORK][4];
__device__ float    g_y[IN_F];          // slow path only
__device__ float    g_o[OUT_F] = {};    // zeroed by final block
__device__ unsigned g_done0 = 0u, g_cnt2 = 0u, g_done3 = 0u, g_done4 = 0u;

__device__ __forceinline__ float warp_sum(float v) {
    #pragma unroll
    for (int o = 16; o > 0; o >>= 1) v += __shfl_xor_sync(0xffffffffu, v, o);
    return v;
}
__device__ __forceinline__ float warp_max(float v) {
    #pragma unroll
    for (int o = 16; o > 0; o >>= 1) v = fmaxf(v, __shfl_xor_sync(0xffffffffu, v, o));
    return v;
}

__global__ void __launch_bounds__(NTHR, 1)
fused_gat(const float* __restrict__ X, const float* __restrict__ W,
          const float* __restrict__ a, float* __restrict__ out) {
    const int t = threadIdx.x, bid = blockIdx.x;
    const int warp = t >> 5, lane = t & 31;

    __shared__ float sw[2 * IN_F];
    __shared__ float sbuf[NTHR];
    __shared__ float bmax_sh, gmax_sh;
    __shared__ int   lc_cnt, ovf_sh, ccnt_sh, flag_sh;
    __shared__ int   crows[MAXC];
    __shared__ float cvals[MAXC];
    __shared__ float rsv[MAXC];

    // ================= PRODUCERS: blocks 128..147 compute w = W @ a ========
    if (bid >= NWORK) {
        int pb = bid - NWORK;                            // 0..19
        int base = (pb * 768) / NPROD;
        int end  = ((pb + 1) * 768) / NPROD;             // 38-39 rows each
        for (int row = base + warp; row < end; row += NWPB) {
            float d1 = 0.f, d2 = 0.f;
            #pragma unroll
            for (int q = 0; q < 8; q++) {
                int c = q * 32 + lane;
                float w = W[row * OUT_F + c];
                d1 = fmaf(w, a[c], d1);
                d2 = fmaf(w, a[OUT_F + c], d2);
            }
            d1 = warp_sum(d1); d2 = warp_sum(d2);
            if (lane == 0) { g_w[row] = d1; g_w[IN_F + row] = d2; }
        }
        __syncthreads();
        if (t == 0) { __threadfence(); atomicAdd(&g_done0, 1u); }
        return;
    }

    // ================= WORKERS: blocks 0..127, 4 X-rows per warp ===========
    const int gw = bid * NWPB + warp;                    // 0 .. 2047
    float4 v0[6], v1[6], v2[6], v3[6];
    {
        const float4* p0 = (const float4*)(X + (size_t)(gw)        * IN_F);
        const float4* p1 = (const float4*)(X + (size_t)(gw + 2048) * IN_F);
        const float4* p2 = (const float4*)(X + (size_t)(gw + 4096) * IN_F);
        const float4* p3 = (const float4*)(X + (size_t)(gw + 6144) * IN_F);
        #pragma unroll
        for (int q = 0; q < 6; q++) v0[q] = p0[q * 32 + lane];
        #pragma unroll
        for (int q = 0; q < 6; q++) v1[q] = p1[q * 32 + lane];
        #pragma unroll
        for (int q = 0; q < 6; q++) v2[q] = p2[q * 32 + lane];
        #pragma unroll
        for (int q = 0; q < 6; q++) v3[q] = p3[q * 32 + lane];
    }

    // ---- gate 1: tight spin for the 20 w-producer blocks ----
    if (t == 0) {
        lc_cnt = 0;
        while (*((volatile unsigned*)&g_done0) < NPROD) { }
        __threadfence();
    }
    __syncthreads();
    // stage w into smem (1536 floats, 512 threads: 3 each)
    sw[t] = __ldcg(&g_w[t]);
    sw[t + NTHR] = __ldcg(&g_w[t + NTHR]);
    sw[t + 2 * NTHR] = __ldcg(&g_w[t + 2 * NTHR]);
    __syncthreads();

    {
        float d1r[4] = {0.f, 0.f, 0.f, 0.f};
        float d2r[4] = {0.f, 0.f, 0.f, 0.f};
        #pragma unroll
        for (int q = 0; q < 6; q++) {
            int c = (q * 32 + lane) * 4;
            float w10 = sw[c],        w11 = sw[c+1],      w12 = sw[c+2],      w13 = sw[c+3];
            float w20 = sw[IN_F+c],   w21 = sw[IN_F+c+1], w22 = sw[IN_F+c+2], w23 = sw[IN_F+c+3];
            float4 A = v0[q], B = v1[q], C = v2[q], D = v3[q];
            d1r[0] = fmaf(A.x, w10, d1r[0]); d1r[0] = fmaf(A.y, w11, d1r[0]);
            d1r[0] = fmaf(A.z, w12, d1r[0]); d1r[0] = fmaf(A.w, w13, d1r[0]);
            d2r[0] = fmaf(A.x, w20, d2r[0]); d2r[0] = fmaf(A.y, w21, d2r[0]);
            d2r[0] = fmaf(A.z, w22, d2r[0]); d2r[0] = fmaf(A.w, w23, d2r[0]);
            d1r[1] = fmaf(B.x, w10, d1r[1]); d1r[1] = fmaf(B.y, w11, d1r[1]);
            d1r[1] = fmaf(B.z, w12, d1r[1]); d1r[1] = fmaf(B.w, w13, d1r[1]);
            d2r[1] = fmaf(B.x, w20, d2r[1]); d2r[1] = fmaf(B.y, w21, d2r[1]);
            d2r[1] = fmaf(B.z, w22, d2r[1]); d2r[1] = fmaf(B.w, w23, d2r[1]);
            d1r[2] = fmaf(C.x, w10, d1r[2]); d1r[2] = fmaf(C.y, w11, d1r[2]);
            d1r[2] = fmaf(C.z, w12, d1r[2]); d1r[2] = fmaf(C.w, w13, d1r[2]);
            d2r[2] = fmaf(C.x, w20, d2r[2]); d2r[2] = fmaf(C.y, w21, d2r[2]);
            d2r[2] = fmaf(C.z, w22, d2r[2]); d2r[2] = fmaf(C.w, w23, d2r[2]);
            d1r[3] = fmaf(D.x, w10, d1r[3]); d1r[3] = fmaf(D.y, w11, d1r[3]);
            d1r[3] = fmaf(D.z, w12, d1r[3]); d1r[3] = fmaf(D.w, w13, d1r[3]);
            d2r[3] = fmaf(D.x, w20, d2r[3]); d2r[3] = fmaf(D.y, w21, d2r[3]);
            d2r[3] = fmaf(D.z, w22, d2r[3]); d2r[3] = fmaf(D.w, w23, d2r[3]);
        }
        float s1mx = -INFINITY;
        #pragma unroll
        for (int k = 0; k < 4; k++) {
            d1r[k] = warp_sum(d1r[k]);
            d2r[k] = warp_sum(d2r[k]);
            s1mx = fmaxf(s1mx, d1r[k]);
        }
        if (lane == 0) {
            #pragma unroll
            for (int k = 0; k < 4; k++) {
                g_s1[gw + 2048 * k] = d1r[k];
                g_s2[gw + 2048 * k] = d2r[k];
            }
            sbuf[warp] = s1mx;
        }
        __syncthreads();
        if (warp == 0) {
            float m = (lane < NWPB) ? sbuf[lane] : -INFINITY;
            m = warp_max(m);
            if (lane == 0) bmax_sh = m;
        }
        __syncthreads();
        if (lane == 0) {
            float thr = bmax_sh - THRESH;
            #pragma unroll
            for (int k = 0; k < 4; k++) {
                if (d1r[k] >= thr) {
                    int p = atomicAdd(&lc_cnt, 1);
                    if (p < 4) { crows[p] = gw + 2048 * k; cvals[p] = d1r[k]; }
                }
            }
        }
        __syncthreads();
        if (t == 0) {
            int c = lc_cnt;
            g_scnt[bid] = c;
            #pragma unroll
            for (int k = 0; k < 4; k++)
                if (k < c) { g_srow[bid][k] = crows[k]; g_sval[bid][k] = cvals[k]; }
            __threadfence();
            atomicAdd(&g_cnt2, 1u);
        }
    }
    if (bid >= 24) return;                // only 24 finisher blocks continue

    // ---- prefetch W slice: 2 col-groups x 16 rows in registers (coalesced) ----
    const int kb = bid * 32, g = t >> 8, c = t & 255;    // g in {0,1}
    float wreg[16];
    #pragma unroll
    for (int k = 0; k < 16; k++) wreg[k] = W[(kb + g * 16 + k) * OUT_F + c];

    // ---- gate 2: tight spin for all 128 worker arrivals ----
    if (t == 0) {
        ovf_sh = 0; ccnt_sh = 0;
        while (*((volatile unsigned*)&g_cnt2) < (unsigned)NWORK) { }
        __threadfence();
    }
    __syncthreads();

    // ---- shortlist merge: single pass, filter from registers ----
    {
        float lm = -INFINITY;
        int myc = 0, rrow[4]; float rval[4];
        if (t < NWORK) {
            myc = __ldcg(&g_scnt[t]);
            if (myc > 4) ovf_sh = 1;                     // benign race
            #pragma unroll
            for (int k = 0; k < 4; k++) {
                if (k < myc) {
                    rrow[k] = __ldcg(&g_srow[t][k]);
                    rval[k] = __ldcg(&g_sval[t][k]);
                    lm = fmaxf(lm, rval[k]);
                }
            }
        }
        float wm = warp_max(lm);
        if (lane == 0) sbuf[warp] = wm;
        __syncthreads();
        if (warp == 0) {
            float m = (lane < NWPB) ? sbuf[lane] : -INFINITY;
            m = warp_max(m);
            if (lane == 0) gmax_sh = m;
        }
        __syncthreads();
        if (t < NWORK) {
            float thr = gmax_sh - THRESH;
            #pragma unroll
            for (int k = 0; k < 4; k++) {
                if (k < myc && rval[k] >= thr) {
                    int p = atomicAdd(&ccnt_sh, 1);
                    if (p < MAXC) crows[p] = rrow[k];
                }
            }
        }
        __syncthreads();
    }

    const float* ysrc;
    if (ovf_sh == 0 && ccnt_sh == 1) {
        // ---- FAST PATH: one candidate -> att one-hot -> y = X[row] exactly ----
        ysrc = X + (size_t)crows[0] * IN_F;
    } else {
        // ---- SLOW PATH (rare): block 0 computes exact softmax + y ----
        if (bid == 0) {
            float lmax = -INFINITY;
            for (int i = t; i < N_TOK; i += NTHR)
                lmax = fmaxf(lmax, __ldcg(&g_s1[i]));
            float wm = warp_max(lmax);
            if (lane == 0) sbuf[warp] = wm;
            __syncthreads();
            if (warp == 0) {
                float m = (lane < NWPB) ? sbuf[lane] : -INFINITY;
                m = warp_max(m);
                if (lane == 0) { gmax_sh = m; ccnt_sh = 0; }
            }
            __syncthreads();
            float thr = gmax_sh - THRESH;
            for (int i = t; i < N_TOK; i += NTHR) {
                if (__ldcg(&g_s1[i]) >= thr) {
                    int p = atomicAdd(&ccnt_sh, 1);
                    if (p < MAXC) crows[p] = i;
                }
            }
            __syncthreads();
            int cc = min(ccnt_sh, MAXC);
            for (int s = 0; s < cc; s++) {
                float s1c = __ldcg(&g_s1[crows[s]]);
                float acc = 0.f;
                for (int j = t; j < N_TOK; j += NTHR)
                    acc += fabsf(s1c + __ldcg(&g_s2[j]));
                acc = warp_sum(acc);
                if (lane == 0) sbuf[warp] = acc;
                __syncthreads();
                if (warp == 0) {
                    float v = (lane < NWPB) ? sbuf[lane] : 0.f;
                    v = warp_sum(v);
                    if (lane == 0) rsv[s] = fmaf(C1f * 8192.f, s1c, C2f * v);
                }
                __syncthreads();
            }
            float m = -INFINITY;
            for (int s = 0; s < cc; s++) m = fmaxf(m, rsv[s]);
            float S = 0.f;
            for (int s = 0; s < cc; s++) S += expf(rsv[s] - m);
            float invS = 1.f / S;
            for (int i = t; i < IN_F; i += NTHR) {
                float y = 0.f;
                for (int s = 0; s < cc; s++) {
                    float e = expf(rsv[s] - m);
                    if (e != 0.f)
                        y = fmaf(e * invS, __ldcg(&X[(size_t)crows[s] * IN_F + i]), y);
                }
                g_y[i] = y;
            }
            __threadfence();
            __syncthreads();
            if (t == 0) atomicExch(&g_done3, 1u);
        }
        if (t == 0) {
            while (*((volatile unsigned*)&g_done3) == 0u) { }
            __threadfence();
        }
        __syncthreads();
        ysrc = g_y;
    }

    // ---- P4: o = y @ W (24 blocks x 32 rows); direct atomics, no smem stage ----
    {
        if (t < 32) sbuf[t] = __ldcg(&ysrc[kb + t]);
        __syncthreads();
        float acc = 0.f;
        #pragma unroll
        for (int k = 0; k < 16; k++)
            acc = fmaf(sbuf[g * 16 + k], wreg[k], acc);
        atomicAdd(&g_o[c], acc);                 // both col-groups add directly
        __threadfence();
        __syncthreads();
        if (t == 0) flag_sh = (atomicAdd(&g_done4, 1u) == 23u) ? 1 : 0;
        __syncthreads();
        if (flag_sh) {
            __threadfence();
            if (t < OUT_F) {
                float o = __ldcg(&g_o[t]);
                out[t] = (o > 0.f) ? o : expm1f(o);
                g_o[t] = 0.f;                   // cleanup for next replay
            }
            if (t == 0) { g_done0 = 0u; g_cnt2 = 0u; g_done3 = 0u; g_done4 = 0u; }
        }
    }
}

extern "C" void kernel_launch(void* const* d_in, const int* in_sizes, int n_in,
                              void* d_out, int out_size) {
    const float* X = (const float*)d_in[0];   // [8192, 768]
    const float* W = (const float*)d_in[1];   // [768, 256]
    const float* a = (const float*)d_in[2];   // [512, 1]
    float* out = (float*)d_out;               // [256]

    fused_gat<<<NBLK, NTHR>>>(X, W, a, out);
}